// round 4
// baseline (speedup 1.0000x reference)
#include <cuda_runtime.h>
#include <cstdint>

#define TSEQ   2048
#define DMODEL 1024
#define NHEADS 16
#define DKH    64
#define NBATCH 4
#define NROWS  (NBATCH * TSEQ)   // 8192

typedef unsigned long long u64;

// Scratch
__device__ float g_q[(size_t)NBATCH * NHEADS * TSEQ * DKH];
__device__ float g_k[(size_t)NBATCH * NHEADS * TSEQ * DKH];
__device__ float g_v[(size_t)NBATCH * NHEADS * TSEQ * DKH];
__device__ float g_ctx[(size_t)NROWS * DMODEL];

// ---------------------------------------------------------------------------
// Packed f32x2 helpers (sm_100+ base ISA)
// ---------------------------------------------------------------------------
#define PACK2(d, x, y) \
    asm("mov.b64 %0, {%1, %2};" : "=l"(d) : "r"(__float_as_uint(x)), "r"(__float_as_uint(y)))
#define UNPACK2(x, y, d) do {                                        \
    uint32_t _lo, _hi;                                               \
    asm("mov.b64 {%0, %1}, %2;" : "=r"(_lo), "=r"(_hi) : "l"(d));    \
    (x) = __uint_as_float(_lo); (y) = __uint_as_float(_hi);          \
} while (0)
#define FMA2(d, a, b) \
    asm("fma.rn.f32x2 %0, %1, %2, %0;" : "+l"(d) : "l"(a), "l"(b))
#define MUL2(d, a, b) \
    asm("mul.rn.f32x2 %0, %1, %2;" : "=l"(d) : "l"(a), "l"(b))

// ---------------------------------------------------------------------------
// f32x2 SIMT GEMM: C[M,N] = A[M,K] @ W[K,N] + bias.  M=8192, N=K=1024.
// 128x128 block tile, K-tile 8, 256 threads, 8x8 per-thread (packed over n).
// ---------------------------------------------------------------------------
template <int HEADS_OUT>
__global__ __launch_bounds__(256, 2) void gemm_f2(
    const float* __restrict__ A, const float* __restrict__ W,
    const float* __restrict__ bias, float* __restrict__ C)
{
    __shared__ float As[8][128];   // As[k][m]
    __shared__ float Ws[8][128];   // Ws[k][n]

    const int tid = threadIdx.x;
    const int m0 = blockIdx.y * 128;
    const int n0 = blockIdx.x * 128;
    const int tm = tid >> 4, tn = tid & 15;

    const int la_row = tid >> 1;
    const int la_k   = (tid & 1) << 2;
    const int lw_k   = tid >> 5;
    const int lw_col = (tid & 31) << 2;

    u64 acc2[8][4];
#pragma unroll
    for (int i = 0; i < 8; i++)
#pragma unroll
        for (int j = 0; j < 4; j++) acc2[i][j] = 0ull;

    const float* Aptr = A + (size_t)(m0 + la_row) * DMODEL + la_k;
    const float* Wptr = W + (size_t)lw_k * DMODEL + n0 + lw_col;

    for (int k0 = 0; k0 < DMODEL; k0 += 8) {
        float4 a4 = *(const float4*)(Aptr + k0);
        float4 w4 = *(const float4*)(Wptr + (size_t)k0 * DMODEL);
        __syncthreads();
        As[la_k + 0][la_row] = a4.x;
        As[la_k + 1][la_row] = a4.y;
        As[la_k + 2][la_row] = a4.z;
        As[la_k + 3][la_row] = a4.w;
        *(float4*)&Ws[lw_k][lw_col] = w4;
        __syncthreads();
#pragma unroll
        for (int kk = 0; kk < 8; kk++) {
            float a[8];
            *(float4*)(a)     = *(float4*)&As[kk][tm * 8];
            *(float4*)(a + 4) = *(float4*)&As[kk][tm * 8 + 4];
            ulonglong2 blo = *(ulonglong2*)&Ws[kk][tn * 8];
            ulonglong2 bhi = *(ulonglong2*)&Ws[kk][tn * 8 + 4];
            const u64 b2[4] = {blo.x, blo.y, bhi.x, bhi.y};
#pragma unroll
            for (int i = 0; i < 8; i++) {
                u64 ai;
                PACK2(ai, a[i], a[i]);
#pragma unroll
                for (int j = 0; j < 4; j++)
                    FMA2(acc2[i][j], ai, b2[j]);
            }
        }
    }

#pragma unroll
    for (int i = 0; i < 8; i++) {
        const int m = m0 + tm * 8 + i;
        const int bb = m >> 11;
        const int t = m & (TSEQ - 1);
#pragma unroll
        for (int j = 0; j < 4; j++) {
            const int n = n0 + tn * 8 + 2 * j;
            const float2 b2v = *(const float2*)(bias + n);
            float vx, vy;
            UNPACK2(vx, vy, acc2[i][j]);
            float2 v = make_float2(vx + b2v.x, vy + b2v.y);
            if (HEADS_OUT) {
                const int h = n >> 6, dd = n & 63;
                *(float2*)(C + (((size_t)(bb * NHEADS + h) * TSEQ + t) << 6) + dd) = v;
            } else {
                *(float2*)(C + (size_t)m * DMODEL + n) = v;
            }
        }
    }
}

// ---------------------------------------------------------------------------
// Flash attention, packed f32x2 inner products.
// One block = one (b,h) x 128-query tile, key tiles of 64, 256 threads.
// QK^T: accumulate row-pairs (Q pairs free from d-major smem; K broadcast).
// PV:   accumulate dd-pairs (V pairs free from row-major smem; P broadcast).
// ---------------------------------------------------------------------------
#define SMEM_FLOATS (64 * 128 + 64 * 64 + 64 * 68 + 128 * 68)
#define SMEM_BYTES  (SMEM_FLOATS * 4)

__global__ __launch_bounds__(256, 2) void attn_kernel(
    const float* __restrict__ Q, const float* __restrict__ K,
    const float* __restrict__ V, float* __restrict__ ctx)
{
    extern __shared__ float sm[];
    float* Qs = sm;                  // [64 d][128 r]
    float* Ks = Qs + 64 * 128;       // [64 d][64 c]
    float* Vs = Ks + 64 * 64;        // [64 j][68 d]
    float* Ps = Vs + 64 * 68;        // [128 i][68 j]

    const int tid = threadIdx.x;
    const int tx = tid & 15, ty = tid >> 4;
    const int r0 = ty * 8, c0 = tx * 4;
    const int bh = blockIdx.y;
    const int q0 = blockIdx.x * 128;

    const float* Qg = Q + (size_t)bh * TSEQ * DKH;
    const float* Kg = K + (size_t)bh * TSEQ * DKH;
    const float* Vg = V + (size_t)bh * TSEQ * DKH;

    // Load Q tile transposed (d-major)
    for (int idx = tid; idx < 128 * 16; idx += 256) {
        const int r = idx & 127, d4 = idx >> 7;
        float4 q4 = *(const float4*)&Qg[(size_t)(q0 + r) * DKH + d4 * 4];
        Qs[(d4 * 4 + 0) * 128 + r] = q4.x;
        Qs[(d4 * 4 + 1) * 128 + r] = q4.y;
        Qs[(d4 * 4 + 2) * 128 + r] = q4.z;
        Qs[(d4 * 4 + 3) * 128 + r] = q4.w;
    }

    float m_i[8], l_i[8];
    u64 O2[8][2];   // per-row packed pairs over dd: {c0,c0+1},{c0+2,c0+3}
#pragma unroll
    for (int i = 0; i < 8; i++) {
        m_i[i] = -1e30f; l_i[i] = 0.f;
        O2[i][0] = 0ull; O2[i][1] = 0ull;
    }

    for (int kt = 0; kt < TSEQ / 64; kt++) {
        __syncthreads();
        // K tile, transposed (d-major)
        for (int idx = tid; idx < 64 * 16; idx += 256) {
            const int c = idx & 63, d4 = idx >> 6;
            float4 k4 = *(const float4*)&Kg[(size_t)(kt * 64 + c) * DKH + d4 * 4];
            Ks[(d4 * 4 + 0) * 64 + c] = k4.x;
            Ks[(d4 * 4 + 1) * 64 + c] = k4.y;
            Ks[(d4 * 4 + 2) * 64 + c] = k4.z;
            Ks[(d4 * 4 + 3) * 64 + c] = k4.w;
        }
        // V tile, row-major
        for (int idx = tid; idx < 64 * 16; idx += 256) {
            const int j = idx >> 4, c4 = idx & 15;
            *(float4*)&Vs[j * 68 + c4 * 4] =
                *(const float4*)&Vg[(size_t)(kt * 64 + j) * DKH + c4 * 4];
        }
        __syncthreads();

        // S = Q K^T, packed over row-pairs: s2[rp][cc] = {s[2rp][cc], s[2rp+1][cc]}
        u64 s2[4][4];
#pragma unroll
        for (int rp = 0; rp < 4; rp++)
#pragma unroll
            for (int cc = 0; cc < 4; cc++) s2[rp][cc] = 0ull;

#pragma unroll 8
        for (int d = 0; d < 64; d++) {
            ulonglong2 qa = *(ulonglong2*)&Qs[d * 128 + r0];       // {q0q1,q2q3}
            ulonglong2 qb = *(ulonglong2*)&Qs[d * 128 + r0 + 4];   // {q4q5,q6q7}
            float4 k4 = *(float4*)&Ks[d * 64 + c0];
            u64 kb[4];
            PACK2(kb[0], k4.x, k4.x);
            PACK2(kb[1], k4.y, k4.y);
            PACK2(kb[2], k4.z, k4.z);
            PACK2(kb[3], k4.w, k4.w);
            const u64 qp[4] = {qa.x, qa.y, qb.x, qb.y};
#pragma unroll
            for (int rp = 0; rp < 4; rp++)
#pragma unroll
                for (int cc = 0; cc < 4; cc++)
                    FMA2(s2[rp][cc], qp[rp], kb[cc]);
        }

        // Unpack scores
        float s[8][4];
#pragma unroll
        for (int rp = 0; rp < 4; rp++)
#pragma unroll
            for (int cc = 0; cc < 4; cc++)
                UNPACK2(s[2 * rp][cc], s[2 * rp + 1][cc], s2[rp][cc]);

        // Online softmax (rows owned by 16-lane groups)
#pragma unroll
        for (int rr = 0; rr < 8; rr++) {
#pragma unroll
            for (int cc = 0; cc < 4; cc++) s[rr][cc] *= 0.125f;
            float mt = fmaxf(fmaxf(s[rr][0], s[rr][1]), fmaxf(s[rr][2], s[rr][3]));
#pragma unroll
            for (int o = 8; o; o >>= 1)
                mt = fmaxf(mt, __shfl_xor_sync(0xffffffffu, mt, o));
            const float mnew = fmaxf(m_i[rr], mt);
            const float corr = __expf(m_i[rr] - mnew);
            m_i[rr] = mnew;
            float rs = 0.f;
#pragma unroll
            for (int cc = 0; cc < 4; cc++) {
                const float p = __expf(s[rr][cc] - mnew);
                s[rr][cc] = p;
                rs += p;
            }
#pragma unroll
            for (int o = 8; o; o >>= 1)
                rs += __shfl_xor_sync(0xffffffffu, rs, o);
            l_i[rr] = l_i[rr] * corr + rs;
            u64 c2;
            PACK2(c2, corr, corr);
            MUL2(O2[rr][0], O2[rr][0], c2);
            MUL2(O2[rr][1], O2[rr][1], c2);
            *(float4*)&Ps[(r0 + rr) * 68 + c0] =
                make_float4(s[rr][0], s[rr][1], s[rr][2], s[rr][3]);
        }
        __syncthreads();

        // O += P V  (V pairs free; P broadcast-packed)
#pragma unroll 4
        for (int j = 0; j < 64; j++) {
            ulonglong2 v2 = *(ulonglong2*)&Vs[j * 68 + c0];  // {v0v1, v2v3}
            float pj[8];
#pragma unroll
            for (int rr = 0; rr < 8; rr++) pj[rr] = Ps[(r0 + rr) * 68 + j];
#pragma unroll
            for (int rr = 0; rr < 8; rr++) {
                u64 p2;
                PACK2(p2, pj[rr], pj[rr]);
                FMA2(O2[rr][0], p2, v2.x);
                FMA2(O2[rr][1], p2, v2.y);
            }
        }
    }

    // Normalize and write ctx in [B, T, DMODEL] layout
    const int b = bh >> 4, h = bh & 15;
#pragma unroll
    for (int rr = 0; rr < 8; rr++) {
        const float inv = 1.f / l_i[rr];
        const int t = q0 + r0 + rr;
        float o0, o1, o2, o3;
        UNPACK2(o0, o1, O2[rr][0]);
        UNPACK2(o2, o3, O2[rr][1]);
        float4 o4 = make_float4(o0 * inv, o1 * inv, o2 * inv, o3 * inv);
        *(float4*)&ctx[((size_t)(b * TSEQ + t)) * DMODEL + h * 64 + c0] = o4;
    }
}

// ---------------------------------------------------------------------------
extern "C" void kernel_launch(void* const* d_in, const int* in_sizes, int n_in,
                              void* d_out, int out_size)
{
    const float* query = (const float*)d_in[0];
    const float* key   = (const float*)d_in[1];
    const float* value = (const float*)d_in[2];
    const float* Wq = (const float*)d_in[3];
    const float* bq = (const float*)d_in[4];
    const float* Wk = (const float*)d_in[5];
    const float* bk = (const float*)d_in[6];
    const float* Wv = (const float*)d_in[7];
    const float* bv = (const float*)d_in[8];
    const float* Wo = (const float*)d_in[9];
    const float* bo = (const float*)d_in[10];
    float* out = (float*)d_out;

    float *qp, *kp, *vp, *cp;
    cudaGetSymbolAddress((void**)&qp, g_q);
    cudaGetSymbolAddress((void**)&kp, g_k);
    cudaGetSymbolAddress((void**)&vp, g_v);
    cudaGetSymbolAddress((void**)&cp, g_ctx);

    cudaFuncSetAttribute(attn_kernel,
                         cudaFuncAttributeMaxDynamicSharedMemorySize, SMEM_BYTES);

    const dim3 gg(DMODEL / 128, NROWS / 128);   // (8, 64)
    gemm_f2<1><<<gg, 256>>>(query, Wq, bq, qp);
    gemm_f2<1><<<gg, 256>>>(key,   Wk, bk, kp);
    gemm_f2<1><<<gg, 256>>>(value, Wv, bv, vp);
    attn_kernel<<<dim3(TSEQ / 128, NBATCH * NHEADS), 256, SMEM_BYTES>>>(qp, kp, vp, cp);
    gemm_f2<0><<<gg, 256>>>(cp, Wo, bo, out);
}

// round 5
// speedup vs baseline: 1.0008x; 1.0008x over previous
#include <cuda_runtime.h>
#include <cstdint>

#define TSEQ   2048
#define DMODEL 1024
#define NHEADS 16
#define DKH    64
#define NBATCH 4
#define NROWS  (NBATCH * TSEQ)   // 8192

typedef unsigned long long u64;

// Scratch
__device__ float g_q[(size_t)NBATCH * NHEADS * TSEQ * DKH];
__device__ float g_k[(size_t)NBATCH * NHEADS * TSEQ * DKH];
__device__ float g_v[(size_t)NBATCH * NHEADS * TSEQ * DKH];
__device__ float g_ctx[(size_t)NROWS * DMODEL];

// ---------------------------------------------------------------------------
// Packed f32x2 helpers (sm_100+ base ISA)
// ---------------------------------------------------------------------------
#define PACK2(d, x, y) \
    asm("mov.b64 %0, {%1, %2};" : "=l"(d) : "r"(__float_as_uint(x)), "r"(__float_as_uint(y)))
#define UNPACK2(x, y, d) do {                                        \
    uint32_t _lo, _hi;                                               \
    asm("mov.b64 {%0, %1}, %2;" : "=r"(_lo), "=r"(_hi) : "l"(d));    \
    (x) = __uint_as_float(_lo); (y) = __uint_as_float(_hi);          \
} while (0)
#define FMA2(d, a, b) \
    asm("fma.rn.f32x2 %0, %1, %2, %0;" : "+l"(d) : "l"(a), "l"(b))
#define MUL2(d, a, b) \
    asm("mul.rn.f32x2 %0, %1, %2;" : "=l"(d) : "l"(a), "l"(b))

// ---------------------------------------------------------------------------
// f32x2 SIMT GEMM: C[M,N] = A[M,K] @ W[K,N] + bias.  M=8192, N=K=1024.
// 128x128 block tile, K-tile 8, 256 threads, 8x8 per-thread (packed over n).
// ---------------------------------------------------------------------------
template <int HEADS_OUT>
__global__ __launch_bounds__(256, 2) void gemm_f2(
    const float* __restrict__ A, const float* __restrict__ W,
    const float* __restrict__ bias, float* __restrict__ C)
{
    __shared__ float As[8][128];   // As[k][m]
    __shared__ float Ws[8][128];   // Ws[k][n]

    const int tid = threadIdx.x;
    const int m0 = blockIdx.y * 128;
    const int n0 = blockIdx.x * 128;
    const int tm = tid >> 4, tn = tid & 15;

    const int la_row = tid >> 1;
    const int la_k   = (tid & 1) << 2;
    const int lw_k   = tid >> 5;
    const int lw_col = (tid & 31) << 2;

    u64 acc2[8][4];
#pragma unroll
    for (int i = 0; i < 8; i++)
#pragma unroll
        for (int j = 0; j < 4; j++) acc2[i][j] = 0ull;

    const float* Aptr = A + (size_t)(m0 + la_row) * DMODEL + la_k;
    const float* Wptr = W + (size_t)lw_k * DMODEL + n0 + lw_col;

    for (int k0 = 0; k0 < DMODEL; k0 += 8) {
        float4 a4 = *(const float4*)(Aptr + k0);
        float4 w4 = *(const float4*)(Wptr + (size_t)k0 * DMODEL);
        __syncthreads();
        As[la_k + 0][la_row] = a4.x;
        As[la_k + 1][la_row] = a4.y;
        As[la_k + 2][la_row] = a4.z;
        As[la_k + 3][la_row] = a4.w;
        *(float4*)&Ws[lw_k][lw_col] = w4;
        __syncthreads();
#pragma unroll
        for (int kk = 0; kk < 8; kk++) {
            float a[8];
            *(float4*)(a)     = *(float4*)&As[kk][tm * 8];
            *(float4*)(a + 4) = *(float4*)&As[kk][tm * 8 + 4];
            ulonglong2 blo = *(ulonglong2*)&Ws[kk][tn * 8];
            ulonglong2 bhi = *(ulonglong2*)&Ws[kk][tn * 8 + 4];
            const u64 b2[4] = {blo.x, blo.y, bhi.x, bhi.y};
#pragma unroll
            for (int i = 0; i < 8; i++) {
                u64 ai;
                PACK2(ai, a[i], a[i]);
#pragma unroll
                for (int j = 0; j < 4; j++)
                    FMA2(acc2[i][j], ai, b2[j]);
            }
        }
    }

#pragma unroll
    for (int i = 0; i < 8; i++) {
        const int m = m0 + tm * 8 + i;
        const int bb = m >> 11;
        const int t = m & (TSEQ - 1);
#pragma unroll
        for (int j = 0; j < 4; j++) {
            const int n = n0 + tn * 8 + 2 * j;
            const float2 b2v = *(const float2*)(bias + n);
            float vx, vy;
            UNPACK2(vx, vy, acc2[i][j]);
            float2 v = make_float2(vx + b2v.x, vy + b2v.y);
            if (HEADS_OUT) {
                const int h = n >> 6, dd = n & 63;
                *(float2*)(C + (((size_t)(bb * NHEADS + h) * TSEQ + t) << 6) + dd) = v;
            } else {
                *(float2*)(C + (size_t)m * DMODEL + n) = v;
            }
        }
    }
}

// ---------------------------------------------------------------------------
// Flash attention, packed f32x2 inner products.
// One block = one (b,h) x 128-query tile, key tiles of 64, 256 threads.
// QK^T: accumulate row-pairs (Q pairs free from d-major smem; K broadcast).
// PV:   accumulate dd-pairs (V pairs free from row-major smem; P broadcast).
// ---------------------------------------------------------------------------
#define SMEM_FLOATS (64 * 128 + 64 * 64 + 64 * 68 + 128 * 68)
#define SMEM_BYTES  (SMEM_FLOATS * 4)

__global__ __launch_bounds__(256, 2) void attn_kernel(
    const float* __restrict__ Q, const float* __restrict__ K,
    const float* __restrict__ V, float* __restrict__ ctx)
{
    extern __shared__ float sm[];
    float* Qs = sm;                  // [64 d][128 r]
    float* Ks = Qs + 64 * 128;       // [64 d][64 c]
    float* Vs = Ks + 64 * 64;        // [64 j][68 d]
    float* Ps = Vs + 64 * 68;        // [128 i][68 j]

    const int tid = threadIdx.x;
    const int tx = tid & 15, ty = tid >> 4;
    const int r0 = ty * 8, c0 = tx * 4;
    const int bh = blockIdx.y;
    const int q0 = blockIdx.x * 128;

    const float* Qg = Q + (size_t)bh * TSEQ * DKH;
    const float* Kg = K + (size_t)bh * TSEQ * DKH;
    const float* Vg = V + (size_t)bh * TSEQ * DKH;

    // Load Q tile transposed (d-major)
    for (int idx = tid; idx < 128 * 16; idx += 256) {
        const int r = idx & 127, d4 = idx >> 7;
        float4 q4 = *(const float4*)&Qg[(size_t)(q0 + r) * DKH + d4 * 4];
        Qs[(d4 * 4 + 0) * 128 + r] = q4.x;
        Qs[(d4 * 4 + 1) * 128 + r] = q4.y;
        Qs[(d4 * 4 + 2) * 128 + r] = q4.z;
        Qs[(d4 * 4 + 3) * 128 + r] = q4.w;
    }

    float m_i[8], l_i[8];
    u64 O2[8][2];   // per-row packed pairs over dd: {c0,c0+1},{c0+2,c0+3}
#pragma unroll
    for (int i = 0; i < 8; i++) {
        m_i[i] = -1e30f; l_i[i] = 0.f;
        O2[i][0] = 0ull; O2[i][1] = 0ull;
    }

    for (int kt = 0; kt < TSEQ / 64; kt++) {
        __syncthreads();
        // K tile, transposed (d-major)
        for (int idx = tid; idx < 64 * 16; idx += 256) {
            const int c = idx & 63, d4 = idx >> 6;
            float4 k4 = *(const float4*)&Kg[(size_t)(kt * 64 + c) * DKH + d4 * 4];
            Ks[(d4 * 4 + 0) * 64 + c] = k4.x;
            Ks[(d4 * 4 + 1) * 64 + c] = k4.y;
            Ks[(d4 * 4 + 2) * 64 + c] = k4.z;
            Ks[(d4 * 4 + 3) * 64 + c] = k4.w;
        }
        // V tile, row-major
        for (int idx = tid; idx < 64 * 16; idx += 256) {
            const int j = idx >> 4, c4 = idx & 15;
            *(float4*)&Vs[j * 68 + c4 * 4] =
                *(const float4*)&Vg[(size_t)(kt * 64 + j) * DKH + c4 * 4];
        }
        __syncthreads();

        // S = Q K^T, packed over row-pairs: s2[rp][cc] = {s[2rp][cc], s[2rp+1][cc]}
        u64 s2[4][4];
#pragma unroll
        for (int rp = 0; rp < 4; rp++)
#pragma unroll
            for (int cc = 0; cc < 4; cc++) s2[rp][cc] = 0ull;

#pragma unroll 8
        for (int d = 0; d < 64; d++) {
            ulonglong2 qa = *(ulonglong2*)&Qs[d * 128 + r0];       // {q0q1,q2q3}
            ulonglong2 qb = *(ulonglong2*)&Qs[d * 128 + r0 + 4];   // {q4q5,q6q7}
            float4 k4 = *(float4*)&Ks[d * 64 + c0];
            u64 kb[4];
            PACK2(kb[0], k4.x, k4.x);
            PACK2(kb[1], k4.y, k4.y);
            PACK2(kb[2], k4.z, k4.z);
            PACK2(kb[3], k4.w, k4.w);
            const u64 qp[4] = {qa.x, qa.y, qb.x, qb.y};
#pragma unroll
            for (int rp = 0; rp < 4; rp++)
#pragma unroll
                for (int cc = 0; cc < 4; cc++)
                    FMA2(s2[rp][cc], qp[rp], kb[cc]);
        }

        // Unpack scores
        float s[8][4];
#pragma unroll
        for (int rp = 0; rp < 4; rp++)
#pragma unroll
            for (int cc = 0; cc < 4; cc++)
                UNPACK2(s[2 * rp][cc], s[2 * rp + 1][cc], s2[rp][cc]);

        // Online softmax (rows owned by 16-lane groups)
#pragma unroll
        for (int rr = 0; rr < 8; rr++) {
#pragma unroll
            for (int cc = 0; cc < 4; cc++) s[rr][cc] *= 0.125f;
            float mt = fmaxf(fmaxf(s[rr][0], s[rr][1]), fmaxf(s[rr][2], s[rr][3]));
#pragma unroll
            for (int o = 8; o; o >>= 1)
                mt = fmaxf(mt, __shfl_xor_sync(0xffffffffu, mt, o));
            const float mnew = fmaxf(m_i[rr], mt);
            const float corr = __expf(m_i[rr] - mnew);
            m_i[rr] = mnew;
            float rs = 0.f;
#pragma unroll
            for (int cc = 0; cc < 4; cc++) {
                const float p = __expf(s[rr][cc] - mnew);
                s[rr][cc] = p;
                rs += p;
            }
#pragma unroll
            for (int o = 8; o; o >>= 1)
                rs += __shfl_xor_sync(0xffffffffu, rs, o);
            l_i[rr] = l_i[rr] * corr + rs;
            u64 c2;
            PACK2(c2, corr, corr);
            MUL2(O2[rr][0], O2[rr][0], c2);
            MUL2(O2[rr][1], O2[rr][1], c2);
            *(float4*)&Ps[(r0 + rr) * 68 + c0] =
                make_float4(s[rr][0], s[rr][1], s[rr][2], s[rr][3]);
        }
        __syncthreads();

        // O += P V  (V pairs free; P broadcast-packed)
#pragma unroll 4
        for (int j = 0; j < 64; j++) {
            ulonglong2 v2 = *(ulonglong2*)&Vs[j * 68 + c0];  // {v0v1, v2v3}
            float pj[8];
#pragma unroll
            for (int rr = 0; rr < 8; rr++) pj[rr] = Ps[(r0 + rr) * 68 + j];
#pragma unroll
            for (int rr = 0; rr < 8; rr++) {
                u64 p2;
                PACK2(p2, pj[rr], pj[rr]);
                FMA2(O2[rr][0], p2, v2.x);
                FMA2(O2[rr][1], p2, v2.y);
            }
        }
    }

    // Normalize and write ctx in [B, T, DMODEL] layout
    const int b = bh >> 4, h = bh & 15;
#pragma unroll
    for (int rr = 0; rr < 8; rr++) {
        const float inv = 1.f / l_i[rr];
        const int t = q0 + r0 + rr;
        float o0, o1, o2, o3;
        UNPACK2(o0, o1, O2[rr][0]);
        UNPACK2(o2, o3, O2[rr][1]);
        float4 o4 = make_float4(o0 * inv, o1 * inv, o2 * inv, o3 * inv);
        *(float4*)&ctx[((size_t)(b * TSEQ + t)) * DMODEL + h * 64 + c0] = o4;
    }
}

// ---------------------------------------------------------------------------
extern "C" void kernel_launch(void* const* d_in, const int* in_sizes, int n_in,
                              void* d_out, int out_size)
{
    const float* query = (const float*)d_in[0];
    const float* key   = (const float*)d_in[1];
    const float* value = (const float*)d_in[2];
    const float* Wq = (const float*)d_in[3];
    const float* bq = (const float*)d_in[4];
    const float* Wk = (const float*)d_in[5];
    const float* bk = (const float*)d_in[6];
    const float* Wv = (const float*)d_in[7];
    const float* bv = (const float*)d_in[8];
    const float* Wo = (const float*)d_in[9];
    const float* bo = (const float*)d_in[10];
    float* out = (float*)d_out;

    float *qp, *kp, *vp, *cp;
    cudaGetSymbolAddress((void**)&qp, g_q);
    cudaGetSymbolAddress((void**)&kp, g_k);
    cudaGetSymbolAddress((void**)&vp, g_v);
    cudaGetSymbolAddress((void**)&cp, g_ctx);

    cudaFuncSetAttribute(attn_kernel,
                         cudaFuncAttributeMaxDynamicSharedMemorySize, SMEM_BYTES);

    const dim3 gg(DMODEL / 128, NROWS / 128);   // (8, 64)
    gemm_f2<1><<<gg, 256>>>(query, Wq, bq, qp);
    gemm_f2<1><<<gg, 256>>>(key,   Wk, bk, kp);
    gemm_f2<1><<<gg, 256>>>(value, Wv, bv, vp);
    attn_kernel<<<dim3(TSEQ / 128, NBATCH * NHEADS), 256, SMEM_BYTES>>>(qp, kp, vp, cp);
    gemm_f2<0><<<gg, 256>>>(cp, Wo, bo, out);
}